// round 7
// baseline (speedup 1.0000x reference)
#include <cuda_runtime.h>
#include <cuda_bf16.h>
#include <math.h>
#include <stdint.h>

#define B_   4
#define T_   4096
#define C_   1024
#define H_   4096
#define E_   8
#define CAP_ 1024
#define G_   32
#define BK_  32
#define S_   40            // A smem row stride (elements), conflict-free for LDSM
#define SB_  136           // B smem row stride (elements), conflict-free for LDSM.trans

#define ABUF_ (128 * S_)   // 5120 elems per A stage buffer
#define BBUF_ (BK_ * SB_)  // 4352 elems per B stage buffer
// dsm layout (elems): Ah[2][ABUF_] | Al[2][ABUF_] | Bh[2][BBUF_] | Bl[2][BBUF_]
#define SMEM_ELEMS_ (4 * ABUF_ + 4 * BBUF_)
#define SMEM_BYTES_ (SMEM_ELEMS_ * 2)              // 75776

// ======== scratch: EXACTLY round-5/6's set (proven to load & run) ========
__device__ float g_probs[B_ * E_ * T_];
__device__ float g_topp[G_ * CAP_];
__device__ int   g_topi[G_ * CAP_];
__device__ float g_h[(size_t)G_ * CAP_ * H_];     // 512 MB fp32 hidden acts

// ======== helpers ========
__device__ __forceinline__ uint32_t smem_u32(const void* p) {
    uint32_t a;
    asm("{ .reg .u64 t; cvta.to.shared.u64 t, %1; cvt.u32.u64 %0, t; }" : "=r"(a) : "l"(p));
    return a;
}
__device__ __forceinline__ void split_bf16(float v, __nv_bfloat16& h, __nv_bfloat16& l) {
    h = __float2bfloat16(v);
    l = __float2bfloat16(v - __bfloat162float(h));
}
__device__ __forceinline__ float gelu_f(float v) {
    return 0.5f * v * (1.0f + erff(v * 0.70710678118654752f));
}
__device__ __forceinline__ void mma16816(float* d, const uint32_t* a, const uint32_t* b) {
    asm volatile("mma.sync.aligned.m16n8k16.row.col.f32.bf16.bf16.f32 "
        "{%0,%1,%2,%3}, {%4,%5,%6,%7}, {%8,%9}, {%0,%1,%2,%3};"
        : "+f"(d[0]), "+f"(d[1]), "+f"(d[2]), "+f"(d[3])
        : "r"(a[0]), "r"(a[1]), "r"(a[2]), "r"(a[3]), "r"(b[0]), "r"(b[1]));
}
#define LDSM_X4(r, addr) \
    asm volatile("ldmatrix.sync.aligned.m8n8.x4.shared.b16 {%0,%1,%2,%3}, [%4];" \
        : "=r"((r)[0]), "=r"((r)[1]), "=r"((r)[2]), "=r"((r)[3]) : "r"(addr))
#define LDSM_X4_T(r, addr) \
    asm volatile("ldmatrix.sync.aligned.m8n8.x4.trans.shared.b16 {%0,%1,%2,%3}, [%4];" \
        : "=r"((r)[0]), "=r"((r)[1]), "=r"((r)[2]), "=r"((r)[3]) : "r"(addr))

// ======== gate + softmax (identical, proven) ========
__global__ __launch_bounds__(256) void gate_kernel(const float* __restrict__ x,
                                                   const float* __restrict__ gw) {
    __shared__ float sgw[E_][C_];
    for (int i = threadIdx.x; i < C_ * E_; i += 256) {
        int c = i >> 3, e = i & 7;
        sgw[e][c] = gw[i];
    }
    __syncthreads();
    const int warp = threadIdx.x >> 5, lane = threadIdx.x & 31;
    const int token = blockIdx.x * 8 + warp;
    const float* xrow = x + (size_t)token * C_;
    float acc[E_];
#pragma unroll
    for (int e = 0; e < E_; e++) acc[e] = 0.f;
    for (int c = lane; c < C_; c += 32) {
        float xv = xrow[c];
#pragma unroll
        for (int e = 0; e < E_; e++) acc[e] = fmaf(xv, sgw[e][c], acc[e]);
    }
#pragma unroll
    for (int off = 16; off > 0; off >>= 1)
#pragma unroll
        for (int e = 0; e < E_; e++) acc[e] += __shfl_xor_sync(0xffffffffu, acc[e], off);
    if (lane == 0) {
        float mx = acc[0];
#pragma unroll
        for (int e = 1; e < E_; e++) mx = fmaxf(mx, acc[e]);
        float s = 0.f, ex[E_];
#pragma unroll
        for (int e = 0; e < E_; e++) { ex[e] = expf(acc[e] - mx); s += ex[e]; }
        float inv = 1.0f / s;
        const int b = token >> 12, t = token & (T_ - 1);
#pragma unroll
        for (int e = 0; e < E_; e++)
            g_probs[((size_t)(b * E_ + e)) * T_ + t] = ex[e] * inv;
    }
}

// ======== top-k bitonic (identical, proven) ========
__global__ __launch_bounds__(1024) void topk_kernel() {
    __shared__ unsigned long long keys[T_];
    const int g = blockIdx.x;
    const float* p = g_probs + (size_t)g * T_;
    for (int i = threadIdx.x; i < T_; i += 1024) {
        unsigned pb = __float_as_uint(p[i]);
        keys[i] = ((unsigned long long)pb << 32) | (unsigned)(0xFFFFFFFFu - (unsigned)i);
    }
    __syncthreads();
    for (int k = 2; k <= T_; k <<= 1)
        for (int j = k >> 1; j > 0; j >>= 1) {
            for (int i = threadIdx.x; i < T_; i += 1024) {
                int ixj = i ^ j;
                if (ixj > i) {
                    unsigned long long a = keys[i], bb = keys[ixj];
                    bool dsc = ((i & k) == 0);
                    if (dsc ? (a < bb) : (a > bb)) { keys[i] = bb; keys[ixj] = a; }
                }
            }
            __syncthreads();
        }
    for (int i = threadIdx.x; i < CAP_; i += 1024) {
        unsigned long long kv = keys[i];
        g_topp[(size_t)g * CAP_ + i] = __uint_as_float((unsigned)(kv >> 32));
        g_topi[(size_t)g * CAP_ + i] = (int)(0xFFFFFFFFu - (unsigned)kv);
    }
}

// ======== stage store: split-convert fa/fb and store into stage buffer s ========
__device__ __forceinline__ void stage_store(__nv_bfloat16* base, int s,
                                            const float* fa, const float* fb,
                                            int soA, int soB) {
    __nv_bfloat16* sAh = base + s * ABUF_;
    __nv_bfloat16* sAl = base + 2 * ABUF_ + s * ABUF_;
    __nv_bfloat16* sBh = base + 4 * ABUF_ + s * BBUF_;
    __nv_bfloat16* sBl = base + 4 * ABUF_ + 2 * BBUF_ + s * BBUF_;
    __align__(16) __nv_bfloat16 hb[16], lb[16];
#pragma unroll
    for (int j = 0; j < 16; j++) split_bf16(fa[j], hb[j], lb[j]);
    *(uint4*)(sAh + soA)     = ((uint4*)hb)[0];
    *(uint4*)(sAh + soA + 8) = ((uint4*)hb)[1];
    *(uint4*)(sAl + soA)     = ((uint4*)lb)[0];
    *(uint4*)(sAl + soA + 8) = ((uint4*)lb)[1];
#pragma unroll
    for (int j = 0; j < 16; j++) split_bf16(fb[j], hb[j], lb[j]);
    *(uint4*)(sBh + soB)     = ((uint4*)hb)[0];
    *(uint4*)(sBh + soB + 8) = ((uint4*)hb)[1];
    *(uint4*)(sBl + soB)     = ((uint4*)lb)[0];
    *(uint4*)(sBl + soB + 8) = ((uint4*)lb)[1];
}

// ======== MMA tile core: double-buffered stages, one barrier per K-block ========
// CTA 128x128, BK=32, 256 threads / 8 warps (4m x 2n, warp tile 32x64).
__device__ __forceinline__ void mma_tile(
    const float* __restrict__ aRow, const float* __restrict__ bPos,
    int nstride, int nkb, __nv_bfloat16* base, float acc[2][8][4])
{
    const int tid  = threadIdx.x;
    const int warp = tid >> 5, lane = tid & 31;
    const int m_off = (warp >> 1) * 32;
    const int n_off = (warp & 1) * 64;
    const int soA = (tid >> 1) * S_ + (tid & 1) * 16;
    const int soB = (tid >> 3) * SB_ + (tid & 7) * 16;

    const uint32_t ub = smem_u32(base);
    const uint32_t oAl = 2u * ABUF_ * 2u;
    const uint32_t oBh = 4u * ABUF_ * 2u;
    const uint32_t oBl = (4u * ABUF_ + 2u * BBUF_) * 2u;
    const uint32_t aoff = (uint32_t)(((m_off + (lane & 15)) * S_ + ((lane & 16) ? 8 : 0)) * 2);
    const uint32_t boff = (uint32_t)(((lane & 15) * SB_ + n_off + ((lane & 16) ? 8 : 0)) * 2);

    float fa[16], fb[16];
#pragma unroll
    for (int q = 0; q < 4; q++) *(float4*)(fa + 4 * q) = ((const float4*)aRow)[q];
#pragma unroll
    for (int q = 0; q < 4; q++) *(float4*)(fb + 4 * q) = ((const float4*)bPos)[q];

    stage_store(base, 0, fa, fb, soA, soB);
    __syncthreads();

    if (nkb > 1) {
        const float* an = aRow + BK_;
        const float* bn = bPos + (size_t)BK_ * nstride;
#pragma unroll
        for (int q = 0; q < 4; q++) *(float4*)(fa + 4 * q) = ((const float4*)an)[q];
#pragma unroll
        for (int q = 0; q < 4; q++) *(float4*)(fb + 4 * q) = ((const float4*)bn)[q];
    }

    for (int kb = 0; kb < nkb; kb++) {
        const int s = kb & 1;
        if (kb + 1 < nkb) {
            stage_store(base, s ^ 1, fa, fb, soA, soB);   // buf s^1 free: readers synced
            if (kb + 2 < nkb) {
                const float* an = aRow + (size_t)(kb + 2) * BK_;
                const float* bn = bPos + (size_t)(kb + 2) * BK_ * nstride;
#pragma unroll
                for (int q = 0; q < 4; q++) *(float4*)(fa + 4 * q) = ((const float4*)an)[q];
#pragma unroll
                for (int q = 0; q < 4; q++) *(float4*)(fb + 4 * q) = ((const float4*)bn)[q];
            }
        }

        const uint32_t uAh = ub + (uint32_t)s * ABUF_ * 2u;
        const uint32_t uAl = ub + oAl + (uint32_t)s * ABUF_ * 2u;
        const uint32_t uBh = ub + oBh + (uint32_t)s * BBUF_ * 2u;
        const uint32_t uBl = ub + oBl + (uint32_t)s * BBUF_ * 2u;
#pragma unroll
        for (int ks = 0; ks < BK_; ks += 16) {
            uint32_t ah[2][4], al[2][4];
#pragma unroll
            for (int mt = 0; mt < 2; mt++) {
                const uint32_t aadd = aoff + (uint32_t)((mt * 16 * S_ + ks) * 2);
                LDSM_X4(ah[mt], uAh + aadd);
                LDSM_X4(al[mt], uAl + aadd);
            }
#pragma unroll
            for (int pair = 0; pair < 4; pair++) {
                uint32_t bh[4], bl[4];
                const uint32_t badd = boff + (uint32_t)((ks * SB_ + pair * 16) * 2);
                LDSM_X4_T(bh, uBh + badd);
                LDSM_X4_T(bl, uBl + badd);
#pragma unroll
                for (int sub = 0; sub < 2; sub++) {
                    const int nt = pair * 2 + sub;
#pragma unroll
                    for (int mt = 0; mt < 2; mt++) {
                        mma16816(acc[mt][nt], ah[mt], bh + 2 * sub);
                        mma16816(acc[mt][nt], ah[mt], bl + 2 * sub);
                        mma16816(acc[mt][nt], al[mt], bh + 2 * sub);
                    }
                }
            }
        }
        __syncthreads();
    }
}

// ======== GEMM1: g_h = gelu(gather(x) @ w1[e]), M=1024 N=4096 K=1024 ========
__global__ __launch_bounds__(256) void gemm1_mma(const float* __restrict__ x,
                                                 const float* __restrict__ w1) {
    extern __shared__ __align__(16) __nv_bfloat16 dsm[];
    __shared__ int s_row[128];

    const int tid = threadIdx.x;
    const int g = blockIdx.z, b = g >> 3, e = g & 7;
    const int m0 = blockIdx.y << 7, n0 = blockIdx.x << 7;
    if (tid < 128) s_row[tid] = g_topi[(size_t)g * CAP_ + m0 + tid];
    __syncthreads();

    const float* aRow = x + ((size_t)(b * T_ + s_row[tid >> 1])) * C_ + (tid & 1) * 16;
    const float* bPos = w1 + (size_t)e * C_ * H_ + (size_t)(tid >> 3) * H_ + n0 + (tid & 7) * 16;

    float acc[2][8][4];
#pragma unroll
    for (int mt = 0; mt < 2; mt++)
#pragma unroll
        for (int nt = 0; nt < 8; nt++)
#pragma unroll
            for (int i = 0; i < 4; i++) acc[mt][nt][i] = 0.f;

    mma_tile(aRow, bPos, H_, C_ / BK_, dsm, acc);

    const int warp = tid >> 5, lane = tid & 31;
    const int gq = lane >> 2, tq = lane & 3;
    const int m_off = (warp >> 1) * 32, n_off = (warp & 1) * 64;
#pragma unroll
    for (int mt = 0; mt < 2; mt++) {
        const int r0l = m_off + mt * 16 + gq;
#pragma unroll
        for (int nt = 0; nt < 8; nt++) {
            const int col = n0 + n_off + nt * 8 + tq * 2;
#pragma unroll
            for (int hrow = 0; hrow < 2; hrow++) {
                const int rl = r0l + hrow * 8;
                float2 v;
                v.x = gelu_f(acc[mt][nt][2 * hrow + 0]);
                v.y = gelu_f(acc[mt][nt][2 * hrow + 1]);
                *(float2*)(g_h + ((size_t)g * CAP_ + m0 + rl) * H_ + col) = v;
            }
        }
    }
}

// ======== GEMM2: out[b,tok] += p * (g_h @ w2[e]), M=1024 N=1024 K=4096 ========
__global__ __launch_bounds__(256) void gemm2_mma(const float* __restrict__ w2,
                                                 float* __restrict__ out) {
    extern __shared__ __align__(16) __nv_bfloat16 dsm[];
    __shared__ int   s_tok[128];
    __shared__ float s_p[128];

    const int tid = threadIdx.x;
    const int g = blockIdx.z, b = g >> 3, e = g & 7;
    const int m0 = blockIdx.y << 7, n0 = blockIdx.x << 7;
    if (tid < 128) {
        s_tok[tid] = g_topi[(size_t)g * CAP_ + m0 + tid];
        s_p[tid]   = g_topp[(size_t)g * CAP_ + m0 + tid];
    }
    __syncthreads();

    const float* aRow = g_h + ((size_t)g * CAP_ + m0 + (tid >> 1)) * H_ + (tid & 1) * 16;
    const float* bPos = w2 + (size_t)e * H_ * C_ + (size_t)(tid >> 3) * C_ + n0 + (tid & 7) * 16;

    float acc[2][8][4];
#pragma unroll
    for (int mt = 0; mt < 2; mt++)
#pragma unroll
        for (int nt = 0; nt < 8; nt++)
#pragma unroll
            for (int i = 0; i < 4; i++) acc[mt][nt][i] = 0.f;

    mma_tile(aRow, bPos, C_, H_ / BK_, dsm, acc);

    const int warp = tid >> 5, lane = tid & 31;
    const int gq = lane >> 2, tq = lane & 3;
    const int m_off = (warp >> 1) * 32, n_off = (warp & 1) * 64;
#pragma unroll
    for (int mt = 0; mt < 2; mt++) {
        const int r0l = m_off + mt * 16 + gq;
#pragma unroll
        for (int nt = 0; nt < 8; nt++) {
            const int col = n0 + n_off + nt * 8 + tq * 2;
#pragma unroll
            for (int hrow = 0; hrow < 2; hrow++) {
                const int rl = r0l + hrow * 8;
                const int tok = s_tok[rl];
                const float p = s_p[rl];
                float* orow = out + ((size_t)b * T_ + tok) * C_ + col;
                atomicAdd(orow,     acc[mt][nt][2 * hrow + 0] * p);
                atomicAdd(orow + 1, acc[mt][nt][2 * hrow + 1] * p);
            }
        }
    }
}

// ======== zero-init output ========
__global__ void zero_kernel(float4* __restrict__ out, int n4) {
    int i = blockIdx.x * blockDim.x + threadIdx.x;
    if (i < n4) out[i] = make_float4(0.f, 0.f, 0.f, 0.f);
}

// ======== launch ========
extern "C" void kernel_launch(void* const* d_in, const int* in_sizes, int n_in,
                              void* d_out, int out_size) {
    const float* x  = (const float*)d_in[0];
    const float* gw = (const float*)d_in[1];
    const float* w1 = (const float*)d_in[2];
    const float* w2 = (const float*)d_in[3];
    float* out = (float*)d_out;

    cudaFuncSetAttribute(gemm1_mma, cudaFuncAttributeMaxDynamicSharedMemorySize, SMEM_BYTES_);
    cudaFuncSetAttribute(gemm2_mma, cudaFuncAttributeMaxDynamicSharedMemorySize, SMEM_BYTES_);

    const int n4 = (B_ * T_ * C_) / 4;
    zero_kernel<<<(n4 + 255) / 256, 256>>>((float4*)out, n4);

    gate_kernel<<<(B_ * T_) / 8, 256>>>(x, gw);
    topk_kernel<<<G_, 1024>>>();

    gemm1_mma<<<dim3(H_ / 128, CAP_ / 128, G_), 256, SMEM_BYTES_>>>(x, w1);
    gemm2_mma<<<dim3(C_ / 128, CAP_ / 128, G_), 256, SMEM_BYTES_>>>(w2, out);
}